// round 6
// baseline (speedup 1.0000x reference)
#include <cuda_runtime.h>
#include <math.h>

#define BB 32
#define SS 256
#define EE 300
#define EP 304
#define HH 256
#define T4H 1024
#define NT 19
#define TSTART 17
#define TSTOP 18

typedef unsigned long long ull;

__device__ __forceinline__ ull fma2(ull a, ull b, ull c) {
    ull d;
    asm("fma.rn.f32x2 %0, %1, %2, %3;" : "=l"(d) : "l"(a), "l"(b), "l"(c));
    return d;
}
__device__ __forceinline__ ull pack2(float lo, float hi) {
    ull r;
    asm("mov.b64 %0, {%1, %2};" : "=l"(r) : "f"(lo), "f"(hi));
    return r;
}
__device__ __forceinline__ float fsigmoid(float x) {
    return 1.0f / (1.0f + __expf(-x));
}
__device__ __forceinline__ float ftanh_fast(float x) {
    return 1.0f - 2.0f / (__expf(2.0f * x) + 1.0f);
}
__device__ __forceinline__ unsigned smem_u32(const void* p) {
    unsigned a;
    asm("{ .reg .u64 t; cvta.to.shared.u64 t, %1; cvt.u32.u64 %0, t; }" : "=r"(a) : "l"(p));
    return a;
}

// ---------------- device scratch (no cudaMalloc allowed) ----------------
__device__ float g_X[(size_t)BB * SS * EP];            // [n][e], n = t*32 + b
__device__ float g_xg[(size_t)2 * SS * T4H * BB];      // [d][t][row][b]
__device__ float g_h[(size_t)2 * SS * HH * BB];        // [d][t][k][b]
__device__ float g_logits[(size_t)BB * SS * NT];       // [b][t][tag]
__device__ int   g_ptr[(size_t)BB * SS * NT];          // viterbi backpointers
__device__ float g_nll[BB];

// ---------------- zero output ----------------
__global__ void zero_out_kernel(float* out, int n) {
    int i = blockIdx.x * blockDim.x + threadIdx.x;
    if (i < n) out[i] = 0.0f;
}

// ---------------- embedding gather + mask -> padded X [8192][304] ----------------
__global__ void embed_kernel(const int* __restrict__ word, const int* __restrict__ mask,
                             const float* __restrict__ emb) {
    int idx = blockIdx.x * blockDim.x + threadIdx.x;
    int total = BB * SS * (EP / 4);
    if (idx >= total) return;
    int n = idx / (EP / 4), q = idx - n * (EP / 4);
    int t = n >> 5, b = n & 31;
    int w = word[b * SS + t];
    float m = (float)mask[b * SS + t];
    int e = q * 4;
    float4 v;
    if (e < EE) {
        float4 ev = *(const float4*)(emb + (size_t)w * EE + e);
        v.x = ev.x * m; v.y = ev.y * m; v.z = ev.z * m; v.w = ev.w * m;
    } else {
        v.x = v.y = v.z = v.w = 0.0f;
    }
    ((float4*)g_X)[(size_t)n * (EP / 4) + q] = v;
}

// ---------------- input-transform GEMM (f32x2): xg = X @ Wih_d.T + bih + bhh ----------------
__global__ __launch_bounds__(256) void gemm_xg_kernel(
    const float* __restrict__ WihF, const float* __restrict__ WihB,
    const float* __restrict__ bihF, const float* __restrict__ bhhF,
    const float* __restrict__ bihB, const float* __restrict__ bhhB) {
    __shared__ ull   As[16][64];
    __shared__ float Xs[16][68];
    int d = blockIdx.z;
    const float* Wih = d ? WihB : WihF;
    const float* bih = d ? bihB : bihF;
    const float* bhh = d ? bhhB : bhhF;
    int m0 = blockIdx.y * 64, n0 = blockIdx.x * 64;
    int tid = threadIdx.x;
    int lm = tid >> 2, kq = (tid & 3) * 4;
    int tx = tid & 15, ty = tid >> 4;
    ull acc[4][2];
#pragma unroll
    for (int i = 0; i < 4; i++) { acc[i][0] = 0ULL; acc[i][1] = 0ULL; }

    for (int e0 = 0; e0 < EP; e0 += 16) {
        float4 a;
        if (e0 + kq < EE) {
            a = *(const float4*)(Wih + (size_t)(m0 + lm) * EE + e0 + kq);
        } else {
            a.x = a.y = a.z = a.w = 0.0f;
        }
        As[kq + 0][lm] = pack2(a.x, a.x);
        As[kq + 1][lm] = pack2(a.y, a.y);
        As[kq + 2][lm] = pack2(a.z, a.z);
        As[kq + 3][lm] = pack2(a.w, a.w);
        float4 xv = *(const float4*)(g_X + (size_t)(n0 + lm) * EP + e0 + kq);
        Xs[kq + 0][lm] = xv.x; Xs[kq + 1][lm] = xv.y; Xs[kq + 2][lm] = xv.z; Xs[kq + 3][lm] = xv.w;
        __syncthreads();
#pragma unroll
        for (int k = 0; k < 16; k++) {
            ulonglong2 w01 = *(const ulonglong2*)&As[k][ty * 4];
            ulonglong2 w23 = *(const ulonglong2*)&As[k][ty * 4 + 2];
            ulonglong2 xx  = *(const ulonglong2*)&Xs[k][tx * 4];
            acc[0][0] = fma2(w01.x, xx.x, acc[0][0]); acc[0][1] = fma2(w01.x, xx.y, acc[0][1]);
            acc[1][0] = fma2(w01.y, xx.x, acc[1][0]); acc[1][1] = fma2(w01.y, xx.y, acc[1][1]);
            acc[2][0] = fma2(w23.x, xx.x, acc[2][0]); acc[2][1] = fma2(w23.x, xx.y, acc[2][1]);
            acc[3][0] = fma2(w23.y, xx.x, acc[3][0]); acc[3][1] = fma2(w23.y, xx.y, acc[3][1]);
        }
        __syncthreads();
    }
#pragma unroll
    for (int i = 0; i < 4; i++) {
        int row = m0 + ty * 4 + i;
        float bias = bih[row] + bhh[row];
        float2 f0 = *(float2*)&acc[i][0];
        float2 f1 = *(float2*)&acc[i][1];
        float vals[4] = {f0.x, f0.y, f1.x, f1.y};
#pragma unroll
        for (int j = 0; j < 4; j++) {
            int n = n0 + tx * 4 + j;
            int tt = n >> 5, bb2 = n & 31;
            g_xg[(((size_t)d * SS + tt) * T4H + row) * BB + bb2] = vals[j] + bias;
        }
    }
}

// ---------------- persistent BiLSTM: clusters of 8, DSMEM h exchange ----------------
// 128 CTAs = 16 clusters x 8. cluster cid: d = cid>>3, bg = cid&7 (batches 4bg..4bg+3).
// CTA rank r owns hidden units [32r,32r+32) -> gate rows gg*256 + 32r + u.
// Whh slice in REGISTERS (64 ull row-pairs per thread). h exchanged via DSMEM,
// double-buffered; sync = split barrier.cluster.arrive/wait (release/acquire per thread).
__global__ __launch_bounds__(256, 1) __cluster_dims__(8, 1, 1)
void lstm_kernel(const float* __restrict__ WhhF, const float* __restrict__ WhhB) {
    __shared__ ull hdup[2][HH * 4];   // [slot][k][b] duplicated {h,h}   (2 x 8KB)
    __shared__ ull part[1024];        // [kq][rp][b] partial gate pairs  (8KB)

    int tid = threadIdx.x;
    unsigned rank;
    asm("mov.u32 %0, %%cluster_ctarank;" : "=r"(rank));
    int cid = blockIdx.x >> 3;
    int d = cid >> 3, bg = cid & 7;
    const float* Whh = d ? WhhB : WhhF;

    int kq = tid >> 6;        // 0..3  (k quarter)
    int rp = tid & 63;        // 0..63 (local row-pair: rows 2rp, 2rp+1)
    int lr0 = 2 * rp, lr1 = 2 * rp + 1;
    int grow0 = (lr0 >> 5) * HH + (int)rank * 32 + (lr0 & 31);
    int grow1 = (lr1 >> 5) * HH + (int)rank * 32 + (lr1 & 31);

    // Whh slice -> registers (one-time)
    ull Wreg[64];
#pragma unroll
    for (int j = 0; j < 64; j++) {
        int k = kq * 64 + j;
        Wreg[j] = pack2(Whh[(size_t)grow0 * HH + k], Whh[(size_t)grow1 * HH + k]);
    }

    // cell-thread mapping (tid < 128): u = hidden unit offset, b = batch offset
    int u = tid >> 2, b = tid & 3;
    float c_reg = 0.0f;
    unsigned hd_base = smem_u32(&hdup[0][0]);

    for (int it = 0; it < SS; it++) {
        int t = d ? (SS - 1 - it) : it;

        // prefetch xg for this step's cell update (latency hidden by wait+GEMV)
        float xgv[4];
        if (tid < 128) {
            const float* xgb = g_xg + ((size_t)(d * SS + t) * T4H) * BB + (size_t)bg * 4 + b;
#pragma unroll
            for (int gg = 0; gg < 4; gg++)
                xgv[gg] = xgb[(size_t)(gg * HH + (int)rank * 32 + u) * BB];
        }

        if (it > 0) {
            // wait for all 8 ranks' h of step it-1 (acquire)
            asm volatile("barrier.cluster.wait.aligned;" ::: "memory");

            const ull* hd = &hdup[(it - 1) & 1][0];
            ull a0 = 0ULL, a1 = 0ULL, a2 = 0ULL, a3 = 0ULL;
#pragma unroll
            for (int j = 0; j < 64; j++) {
                int k = kq * 64 + j;
                ulonglong2 h01 = *(const ulonglong2*)&hd[k * 4];
                ulonglong2 h23 = *(const ulonglong2*)&hd[k * 4 + 2];
                a0 = fma2(Wreg[j], h01.x, a0);
                a1 = fma2(Wreg[j], h01.y, a1);
                a2 = fma2(Wreg[j], h23.x, a2);
                a3 = fma2(Wreg[j], h23.y, a3);
            }
            int idx = (kq * 64 + rp) * 4;
            *(ulonglong2*)&part[idx]     = make_ulonglong2(a0, a1);
            *(ulonglong2*)&part[idx + 2] = make_ulonglong2(a2, a3);
        }
        __syncthreads();

        // cell update (tid < 128): (u, b)
        if (tid < 128) {
            const float* pf = (const float*)part;
            float g[4];
#pragma unroll
            for (int gg = 0; gg < 4; gg++) {
                float s = xgv[gg];
                if (it > 0) {
                    int lr = gg * 32 + u;
                    int rpp = lr >> 1, hf = lr & 1;
#pragma unroll
                    for (int kk = 0; kk < 4; kk++)
                        s += pf[((kk * 64 + rpp) * 4 + b) * 2 + hf];
                }
                g[gg] = s;
            }
            float iv = fsigmoid(g[0]);
            float fv = fsigmoid(g[1]);
            float gv = ftanh_fast(g[2]);
            float ov = fsigmoid(g[3]);
            c_reg = fv * c_reg + iv * gv;
            float hval = ov * ftanh_fast(c_reg);

            // global h for logits (not on critical path)
            g_h[((size_t)(d * SS + t) * HH + rank * 32 + u) * BB + bg * 4 + b] = hval;

            // broadcast duplicated h into all 8 cluster CTAs' hdup[it&1]
            ull hv2 = pack2(hval, hval);
            unsigned loff = hd_base + (unsigned)(((it & 1) * (HH * 4) +
                             ((int)rank * 32 + u) * 4 + b) * 8);
#pragma unroll
            for (int r = 0; r < 8; r++) {
                asm volatile(
                    "{ .reg .b32 ra; mapa.shared::cluster.u32 ra, %0, %1;\n\t"
                    "  st.shared::cluster.b64 [ra], %2; }"
                    :: "r"(loff), "r"(r), "l"(hv2) : "memory");
            }
        }
        __syncthreads();  // part consumed; all cell threads' remote stores issued

        // release-arrive: publishes this step's h to the cluster
        asm volatile("barrier.cluster.arrive.aligned;" ::: "memory");
    }
    // complete final phase before exit
    asm volatile("barrier.cluster.wait.aligned;" ::: "memory");
}

// ---------------- logits: [b][t][tag] = hcat . W_tag[tag] + b_tag ----------------
__global__ __launch_bounds__(256) void logits_kernel(const float* __restrict__ Wtag,
                                                     const float* __restrict__ btag) {
    extern __shared__ float hb[];  // [512 k][32 b]
    int t = blockIdx.x;
    int tid = threadIdx.x;
    for (int dd = 0; dd < 2; dd++) {
        const float4* src = (const float4*)(g_h + (size_t)(dd * SS + t) * HH * BB);
        float4* dst = (float4*)(hb + (size_t)dd * HH * BB);
        for (int i = tid; i < 2048; i += 256) dst[i] = src[i];
    }
    __syncthreads();
    for (int o = tid; o < BB * NT; o += 256) {
        int tag = o >> 5;
        int b = o & 31;
        float acc = btag[tag];
        const float* wr = Wtag + (size_t)tag * (2 * HH);
#pragma unroll 8
        for (int k = 0; k < 2 * HH; k++) acc += hb[k * BB + b] * wr[k];
        g_logits[((size_t)b * SS + t) * NT + tag] = acc;
    }
}

// ---------------- merged CRF forward + Viterbi (grid 32 x 2) ----------------
__global__ void crf_vit_kernel(const int* __restrict__ mask, const int* __restrict__ labels,
                               const float* __restrict__ trans, float* __restrict__ out) {
    __shared__ float tr[NT * NT];
    __shared__ float st[NT];
    int b = blockIdx.x, j = threadIdx.x;
    for (int i = j; i < NT * NT; i += 32) tr[i] = trans[i];
    __syncthreads();

    if (blockIdx.y == 0) {
        if (j < NT) st[j] = g_logits[((size_t)b * SS) * NT + j] + tr[TSTART * NT + j];
        __syncthreads();
        for (int t = 1; t < SS; t++) {
            int mt = mask[b * SS + t];
            float nv = 0.0f;
            if (j < NT) {
                float mx = -1e30f;
#pragma unroll
                for (int i = 0; i < NT; i++) mx = fmaxf(mx, st[i] + tr[i * NT + j]);
                float sum = 0.0f;
#pragma unroll
                for (int i = 0; i < NT; i++) sum += __expf(st[i] + tr[i * NT + j] - mx);
                nv = mx + __logf(sum) + g_logits[((size_t)b * SS + t) * NT + j];
            }
            __syncthreads();
            if (j < NT && mt > 0) st[j] = nv;
            __syncthreads();
        }
        if (j == 0) {
            float mx = -1e30f;
            for (int i = 0; i < NT; i++) mx = fmaxf(mx, st[i] + tr[i * NT + TSTOP]);
            float sum = 0.0f;
            for (int i = 0; i < NT; i++) sum += __expf(st[i] + tr[i * NT + TSTOP] - mx);
            float logZ = mx + __logf(sum);
            float gold = 0.0f;
            int prev = TSTART, len = 0;
            for (int t = 0; t < SS; t++) {
                int lab = labels[b * SS + t];
                if (mask[b * SS + t] > 0) {
                    gold += tr[prev * NT + lab] + g_logits[((size_t)b * SS + t) * NT + lab];
                    len++;
                }
                prev = lab;
            }
            int last = labels[b * SS + len - 1];
            gold += tr[last * NT + TSTOP];
            g_nll[b] = logZ - gold;
        }
    } else {
        if (j < NT) st[j] = g_logits[((size_t)b * SS) * NT + j] + tr[TSTART * NT + j];
        __syncthreads();
        for (int t = 1; t < SS; t++) {
            int mt = mask[b * SS + t];
            float nv = 0.0f;
            int arg = j;
            if (j < NT) {
                float best = -1e30f;
                int bi = 0;
#pragma unroll
                for (int i = 0; i < NT; i++) {
                    float v = st[i] + tr[i * NT + j];
                    if (v > best) { best = v; bi = i; }  // strict '>' => first max (jnp.argmax)
                }
                nv = best + g_logits[((size_t)b * SS + t) * NT + j];
                if (mt > 0) arg = bi;
            }
            __syncthreads();
            if (j < NT) {
                if (mt > 0) st[j] = nv;
                g_ptr[((size_t)b * SS + t) * NT + j] = arg;
            }
            __syncthreads();
        }
        if (j == 0) {
            float best = -1e30f;
            int bl = 0;
            for (int i = 0; i < NT; i++) {
                float v = st[i] + tr[i * NT + TSTOP];
                if (v > best) { best = v; bl = i; }
            }
            int tag = bl;
            for (int t = SS - 1; t >= 1; t--) {
                out[1 + b * SS + t] = (float)(mask[b * SS + t] > 0 ? tag : 0);
                tag = g_ptr[((size_t)b * SS + t) * NT + tag];
            }
            out[1 + b * SS + 0] = (float)(mask[b * SS + 0] > 0 ? tag : 0);
        }
    }
}

__global__ void finalize_kernel(float* out) {
    if (threadIdx.x == 0) {
        float s = 0.0f;
        for (int i = 0; i < BB; i++) s += g_nll[i];
        out[0] = s / (float)BB;
    }
}

extern "C" void kernel_launch(void* const* d_in, const int* in_sizes, int n_in,
                              void* d_out, int out_size) {
    int o = (in_sizes[4] == 1) ? 0 : -1;  // data_type scalar present or dropped
    const int*   word   = (const int*)d_in[0];
    const int*   mask   = (const int*)d_in[1];
    const int*   labels = (const int*)d_in[2];
    const float* emb    = (const float*)d_in[5 + o];
    const float* WihF   = (const float*)d_in[6 + o];
    const float* WhhF   = (const float*)d_in[7 + o];
    const float* bihF   = (const float*)d_in[8 + o];
    const float* bhhF   = (const float*)d_in[9 + o];
    const float* WihB   = (const float*)d_in[10 + o];
    const float* WhhB   = (const float*)d_in[11 + o];
    const float* bihB   = (const float*)d_in[12 + o];
    const float* bhhB   = (const float*)d_in[13 + o];
    const float* Wtag   = (const float*)d_in[14 + o];
    const float* btag   = (const float*)d_in[15 + o];
    const float* trans  = (const float*)d_in[16 + o];
    float* out = (float*)d_out;

    cudaFuncSetAttribute(logits_kernel, cudaFuncAttributeMaxDynamicSharedMemorySize, 65536);

    zero_out_kernel<<<(out_size + 255) / 256, 256>>>(out, out_size);
    embed_kernel<<<(BB * SS * (EP / 4) + 255) / 256, 256>>>(word, mask, emb);
    {
        dim3 grid(BB * SS / 64, T4H / 64, 2);
        gemm_xg_kernel<<<grid, 256>>>(WihF, WihB, bihF, bhhF, bihB, bhhB);
    }
    lstm_kernel<<<128, 256>>>(WhhF, WhhB);
    logits_kernel<<<SS, 256, 65536>>>(Wtag, btag);
    crf_vit_kernel<<<dim3(BB, 2), 32>>>(mask, labels, trans, out);
    finalize_kernel<<<1, 32>>>(out);
}